// round 1
// baseline (speedup 1.0000x reference)
#include <cuda_runtime.h>
#include <cuda_bf16.h>

// Shapes (fixed for this problem)
#define NB 4
#define NQ 512
#define NK 512
#define ND 256
#define NH 256

#define STRIDE 260            // smem row stride (floats): 16B-aligned, bank-friendly

// Scratch: projected queries/keys (B*Q x H) and (B*K x H)
__device__ float g_qh[NB * NQ * NH];
__device__ float g_kh[NB * NK * NH];

__device__ __forceinline__ float tanh_ap(float x) {
    float y;
    asm("tanh.approx.f32 %0, %1;" : "=f"(y) : "f"(x));
    return y;
}

// ---------------------------------------------------------------------------
// Projection GEMM: C[2048x256] = A[2048x256] @ W[256x256]
// blockIdx.z = 0 -> (queries, Wq, g_qh), 1 -> (keys, Wk, g_kh)
// 64x64 output tile per block, BK=16, 256 threads, 4x4 micro-tile.
// ---------------------------------------------------------------------------
__global__ __launch_bounds__(256) void proj_kernel(
    const float* __restrict__ Aq, const float* __restrict__ Wq,
    const float* __restrict__ Ak, const float* __restrict__ Wk)
{
    const float* A; const float* W; float* C;
    if (blockIdx.z == 0) { A = Aq; W = Wq; C = g_qh; }
    else                 { A = Ak; W = Wk; C = g_kh; }

    __shared__ float As[16][68];   // [k][m], transposed on store
    __shared__ float Bs[16][68];   // [k][n]

    const int t    = threadIdx.x;
    const int row0 = blockIdx.y * 64;
    const int col0 = blockIdx.x * 64;
    const int ty   = t >> 4;
    const int tx   = t & 15;

    float acc[4][4] = {};

    for (int k0 = 0; k0 < ND; k0 += 16) {
        // A tile: 64 rows x 16 cols, transpose into As[k][m]
        {
            int r  = t >> 2;           // 0..63
            int c4 = (t & 3) * 4;      // 0,4,8,12
            float4 v = *(const float4*)&A[(row0 + r) * ND + k0 + c4];
            As[c4 + 0][r] = v.x;
            As[c4 + 1][r] = v.y;
            As[c4 + 2][r] = v.z;
            As[c4 + 3][r] = v.w;
        }
        // W tile: 16 rows x 64 cols
        {
            int r  = t >> 4;           // 0..15
            int c4 = (t & 15) * 4;     // 0..60
            *(float4*)&Bs[r][c4] = *(const float4*)&W[(k0 + r) * NH + col0 + c4];
        }
        __syncthreads();
        #pragma unroll
        for (int kk = 0; kk < 16; kk++) {
            float4 av = *(float4*)&As[kk][ty * 4];   // broadcast within half-warp
            float4 bv = *(float4*)&Bs[kk][tx * 4];
            float a_[4] = {av.x, av.y, av.z, av.w};
            float b_[4] = {bv.x, bv.y, bv.z, bv.w};
            #pragma unroll
            for (int i = 0; i < 4; i++)
                #pragma unroll
                for (int j = 0; j < 4; j++)
                    acc[i][j] += a_[i] * b_[j];
        }
        __syncthreads();
    }

    #pragma unroll
    for (int i = 0; i < 4; i++) {
        float4 v = make_float4(acc[i][0], acc[i][1], acc[i][2], acc[i][3]);
        *(float4*)&C[(row0 + ty * 4 + i) * NH + col0 + tx * 4] = v;
    }
}

// ---------------------------------------------------------------------------
// Fused scores (tanh additive) + masked softmax + attn @ values.
// Block = 256 threads = 8 warps = 8 consecutive query rows of one batch b.
// Phase A: per warp, lane = key-in-tile; 32-key kh tiles staged in smem.
// Phase B: register softmax with valid_lens mask (exp underflows to exact 0).
// Phase C: 16-key values tiles staged in smem; 8 outputs per thread (2 float4).
// ---------------------------------------------------------------------------
__global__ __launch_bounds__(256, 2) void attn_kernel(
    const float* __restrict__ values,
    const float* __restrict__ wv,
    const int*   __restrict__ valid_lens,
    float*       __restrict__ out)
{
    __shared__ float sbuf[32 * STRIDE];    // 33280 B: kh tiles (A) / values tiles + attn (C)
    __shared__ float s_qh[8 * NH];         // 8192 B
    __shared__ float s_wv[NH];             // 1024 B
    float* attn_s = &sbuf[16 * STRIDE];    // 8*512 floats, disjoint from 16-key values tile

    const int t    = threadIdx.x;
    const int w    = t >> 5;
    const int lane = t & 31;
    const int qrow = blockIdx.x * 8 + w;           // global row in [0, B*Q)
    const int b    = blockIdx.x >> 6;              // 64 blocks per batch
    const int vl   = valid_lens[b];                // uniform across block

    // Stage qh rows for this block's 8 queries + wv
    #pragma unroll
    for (int rr = 0; rr < 2; rr++) {
        int i = t + 256 * rr;                      // 0..511 float4 slots
        int r = i >> 6;
        int c = (i & 63) * 4;
        *(float4*)&s_qh[r * NH + c] =
            *(const float4*)&g_qh[(blockIdx.x * 8 + r) * NH + c];
    }
    if (t < 64) *(float4*)&s_wv[t * 4] = *(const float4*)&wv[t * 4];
    __syncthreads();

    // ---------------- Phase A: scores ----------------
    float sc[16];
    #pragma unroll
    for (int i = 0; i < 16; i++) sc[i] = -1.0e6f;

    const float* khb = &g_kh[(b * NK) * NH];
    const float* myq = &s_qh[w * NH];

    #pragma unroll
    for (int tile = 0; tile < 16; ++tile) {
        if (tile * 32 < vl) {                      // uniform branch (vl per-block)
            // load kh tile: 32 keys x 256 h  (2048 float4, 8 per thread)
            #pragma unroll
            for (int r = 0; r < 8; ++r) {
                int i  = t + 256 * r;
                int k  = i >> 6;
                int h4 = (i & 63) * 4;
                *(float4*)&sbuf[k * STRIDE + h4] =
                    *(const float4*)&khb[(tile * 32 + k) * NH + h4];
            }
            __syncthreads();

            float acc = 0.f;
            const float* myk = &sbuf[lane * STRIDE];
            #pragma unroll 4
            for (int h = 0; h < NH; h += 4) {
                float4 kv  = *(const float4*)&myk[h];
                float4 qv  = *(const float4*)&myq[h];    // broadcast
                float4 wv4 = *(const float4*)&s_wv[h];   // broadcast
                acc += wv4.x * tanh_ap(qv.x + kv.x);
                acc += wv4.y * tanh_ap(qv.y + kv.y);
                acc += wv4.z * tanh_ap(qv.z + kv.z);
                acc += wv4.w * tanh_ap(qv.w + kv.w);
            }
            sc[tile] = acc;                        // key = tile*32 + lane
            __syncthreads();
        }
    }

    // mask tail keys of the partial tile
    #pragma unroll
    for (int i = 0; i < 16; i++) {
        int k = i * 32 + lane;
        if (k >= vl) sc[i] = -1.0e6f;
    }

    __syncthreads();   // everyone done reading sbuf before attn_s writes overlay it

    // ---------------- Phase B: softmax (registers + shuffles) ----------------
    float mx = -1.0e30f;
    #pragma unroll
    for (int i = 0; i < 16; i++) mx = fmaxf(mx, sc[i]);
    #pragma unroll
    for (int o = 16; o > 0; o >>= 1)
        mx = fmaxf(mx, __shfl_xor_sync(0xffffffffu, mx, o));

    float sum = 0.f;
    #pragma unroll
    for (int i = 0; i < 16; i++) {
        float e = __expf(sc[i] - mx);              // masked -> exact 0 (underflow)
        sum += e;
        attn_s[w * NK + i * 32 + lane] = e;        // unnormalized
    }
    #pragma unroll
    for (int o = 16; o > 0; o >>= 1)
        sum += __shfl_xor_sync(0xffffffffu, sum, o);
    const float inv = 1.0f / sum;

    // ---------------- Phase C: out = attn @ values ----------------
    float4 o0 = make_float4(0.f, 0.f, 0.f, 0.f);
    float4 o1 = make_float4(0.f, 0.f, 0.f, 0.f);
    const int nTilesC = (vl + 15) >> 4;
    const float* vb = &values[(b * NK) * ND];

    for (int tile = 0; tile < nTilesC; ++tile) {
        __syncthreads();                           // tile t reads done / attn_s ready
        // load values tile: 16 keys x 256 d (1024 float4, 4 per thread)
        #pragma unroll
        for (int r = 0; r < 4; ++r) {
            int i  = t + 256 * r;
            int k  = i >> 6;
            int h4 = (i & 63) * 4;
            *(float4*)&sbuf[k * STRIDE + h4] =
                *(const float4*)&vb[(tile * 16 + k) * ND + h4];
        }
        __syncthreads();

        #pragma unroll 4
        for (int kk = 0; kk < 16; ++kk) {
            float a = attn_s[w * NK + tile * 16 + kk];        // broadcast
            float4 v0 = *(const float4*)&sbuf[kk * STRIDE + 4 * lane];
            float4 v1 = *(const float4*)&sbuf[kk * STRIDE + 128 + 4 * lane];
            o0.x += a * v0.x; o0.y += a * v0.y; o0.z += a * v0.z; o0.w += a * v0.w;
            o1.x += a * v1.x; o1.y += a * v1.y; o1.z += a * v1.z; o1.w += a * v1.w;
        }
    }

    o0.x *= inv; o0.y *= inv; o0.z *= inv; o0.w *= inv;
    o1.x *= inv; o1.y *= inv; o1.z *= inv; o1.w *= inv;
    *(float4*)&out[qrow * ND + 4 * lane]       = o0;
    *(float4*)&out[qrow * ND + 128 + 4 * lane] = o1;
}

// ---------------------------------------------------------------------------
extern "C" void kernel_launch(void* const* d_in, const int* in_sizes, int n_in,
                              void* d_out, int out_size)
{
    const float* queries = (const float*)d_in[0];  // (B,Q,D)
    const float* keys    = (const float*)d_in[1];  // (B,K,D)
    const float* values  = (const float*)d_in[2];  // (B,K,D)
    const float* Wq      = (const float*)d_in[3];  // (D,H)
    const float* Wk      = (const float*)d_in[4];  // (D,H)
    const float* wv      = (const float*)d_in[5];  // (H,)
    const int*   vlen    = (const int*)d_in[6];    // (B,) int32
    float* out = (float*)d_out;                    // (B,Q,D)

    (void)in_sizes; (void)n_in; (void)out_size;

    dim3 pgrid(NH / 64, (NB * NQ) / 64, 2);        // 4 x 32 x 2
    proj_kernel<<<pgrid, 256>>>(queries, Wq, keys, Wk);

    attn_kernel<<<(NB * NQ) / 8, 256>>>(values, wv, vlen, out);
}